// round 6
// baseline (speedup 1.0000x reference)
#include <cuda_runtime.h>
#include <cuda_bf16.h>
#include <math.h>

// Problem constants
#define Nn 100000
#define Ee 1600000
#define Ss 4
#define Dd 128
#define Hh 256
#define Pp 10000

#define SCAN_BLOCKS 98   // ceil(100000/1024)

// ---------------- scratch (device globals; no allocations) ----------------
__device__ float g_XW1[(size_t)Nn * Hh];       // X @ W1 (snapshot-invariant)
__device__ float g_H1 [2][(size_t)Nn * Hh];    // relu(layer-1), double-buffered
__device__ float g_HW2[2][(size_t)Nn * Hh];    // H1 @ W2, double-buffered
__device__ float g_ACCS[Ss][(size_t)Pp * Hh];  // per-snapshot post embeddings
// double-buffered CSR
__device__ float g_DINV[2][Nn];
__device__ float g_NRM [2][Ee];
__device__ int   g_CNT [2][Nn];
__device__ int   g_ROWPTR[2][Nn + 1];
__device__ int   g_CURS[2][Nn];
__device__ int   g_COL [2][Ee];
__device__ int   g_BSUM[2][SCAN_BLOCKS];

__device__ __forceinline__ void fma4v(float4& a, const float4 v, const float w) {
    a.x = fmaf(v.x, w, a.x); a.y = fmaf(v.y, w, a.y);
    a.z = fmaf(v.z, w, a.z); a.w = fmaf(v.w, w, a.w);
}

// ------------- tensor-core GEMM (bf16x3 split): C[M,256]=A[M,K]@B[K,256] ---
// mode 0: A = param (node_features), C = g_XW1
// mode 1: A = g_H1[buf],             C = g_HW2[buf]
#define BMg 128
#define BNg 128
#define BKg 32
#define APAD 40   // bf16 row stride (32 + 8) -> conflict-free fragment loads

__device__ __forceinline__ void mma_bf16(
    float& d0, float& d1, float& d2, float& d3,
    unsigned a0, unsigned a1, unsigned a2, unsigned a3,
    unsigned b0, unsigned b1)
{
    asm volatile(
        "mma.sync.aligned.m16n8k16.row.col.f32.bf16.bf16.f32 "
        "{%0,%1,%2,%3}, {%4,%5,%6,%7}, {%8,%9}, {%0,%1,%2,%3};"
        : "+f"(d0), "+f"(d1), "+f"(d2), "+f"(d3)
        : "r"(a0), "r"(a1), "r"(a2), "r"(a3), "r"(b0), "r"(b1));
}

__global__ __launch_bounds__(256) void tc_gemm_kernel(
    const float* __restrict__ Ap, const float* __restrict__ B,
    int mode, int buf, int M, int K)
{
    __shared__ __nv_bfloat16 Ah[BMg][APAD];
    __shared__ __nv_bfloat16 Al[BMg][APAD];
    __shared__ __nv_bfloat16 Bh[BNg][APAD];   // [n][k] layout
    __shared__ __nv_bfloat16 Bl[BNg][APAD];

    const float* A = mode ? g_H1[buf] : Ap;
    float*       C = mode ? g_HW2[buf] : g_XW1;

    int tid = threadIdx.x;                    // 256 threads, 8 warps
    int wid = tid >> 5;
    int lane = tid & 31;
    int warp_m = wid >> 1;                    // 0..3  -> 32-row warp tile
    int warp_n = wid & 1;                     // 0..1  -> 64-col warp tile
    int g = lane >> 2;                        // groupID 0..7
    int c0 = (lane & 3) * 2;                  // 0,2,4,6

    int rowBase = blockIdx.x * BMg;
    int colBase = blockIdx.y * BNg;

    float d[2][8][4];                         // [m frag][n frag][c regs]
#pragma unroll
    for (int im = 0; im < 2; im++)
#pragma unroll
        for (int jn = 0; jn < 8; jn++)
#pragma unroll
            for (int c = 0; c < 4; c++) d[im][jn][c] = 0.f;

    for (int k0 = 0; k0 < K; k0 += BKg) {
        // ---- fill A tile: 128x32 fp32 -> bf16 hi/lo (1024 float4, 4/thread)
#pragma unroll
        for (int l = 0; l < 4; l++) {
            int f = tid + l * 256;            // 0..1023
            int r = f >> 3;                   // 0..127
            int c4 = (f & 7) * 4;             // 0,4,...,28
            float4 v = make_float4(0.f, 0.f, 0.f, 0.f);
            int gr = rowBase + r;
            if (gr < M)
                v = *reinterpret_cast<const float4*>(&A[(size_t)gr * K + k0 + c4]);
            float vv[4] = {v.x, v.y, v.z, v.w};
#pragma unroll
            for (int j = 0; j < 4; j++) {
                __nv_bfloat16 h = __float2bfloat16_rn(vv[j]);
                Ah[r][c4 + j] = h;
                Al[r][c4 + j] = __float2bfloat16_rn(vv[j] - __bfloat162float(h));
            }
        }
        // ---- fill B tile transposed: B[k0..+31][colBase..+127] -> Bh[n][k]
#pragma unroll
        for (int l = 0; l < 4; l++) {
            int f = tid + l * 256;            // 0..1023
            int kk = f >> 5;                  // 0..31
            int n4 = (f & 31) * 4;            // 0,4,...,124
            float4 v = *reinterpret_cast<const float4*>(
                &B[(size_t)(k0 + kk) * Hh + colBase + n4]);
            float vv[4] = {v.x, v.y, v.z, v.w};
#pragma unroll
            for (int j = 0; j < 4; j++) {
                __nv_bfloat16 h = __float2bfloat16_rn(vv[j]);
                Bh[n4 + j][kk] = h;
                Bl[n4 + j][kk] = __float2bfloat16_rn(vv[j] - __bfloat162float(h));
            }
        }
        __syncthreads();

#pragma unroll
        for (int kf = 0; kf < BKg; kf += 16) {
            // A fragments for this k-slice: 2 m-frags, hi+lo (PTX m16n8k16 layout)
            unsigned ah[2][4], al[2][4];
#pragma unroll
            for (int im = 0; im < 2; im++) {
                int br = warp_m * 32 + im * 16 + g;   // rows g / g+8 of frag
                ah[im][0] = *reinterpret_cast<const unsigned*>(&Ah[br][kf + c0]);
                ah[im][1] = *reinterpret_cast<const unsigned*>(&Ah[br + 8][kf + c0]);
                ah[im][2] = *reinterpret_cast<const unsigned*>(&Ah[br][kf + c0 + 8]);
                ah[im][3] = *reinterpret_cast<const unsigned*>(&Ah[br + 8][kf + c0 + 8]);
                al[im][0] = *reinterpret_cast<const unsigned*>(&Al[br][kf + c0]);
                al[im][1] = *reinterpret_cast<const unsigned*>(&Al[br + 8][kf + c0]);
                al[im][2] = *reinterpret_cast<const unsigned*>(&Al[br][kf + c0 + 8]);
                al[im][3] = *reinterpret_cast<const unsigned*>(&Al[br + 8][kf + c0 + 8]);
            }
#pragma unroll
            for (int jn = 0; jn < 8; jn++) {
                int bn = warp_n * 64 + jn * 8 + g;    // n = groupID
                unsigned bh0 = *reinterpret_cast<const unsigned*>(&Bh[bn][kf + c0]);
                unsigned bh1 = *reinterpret_cast<const unsigned*>(&Bh[bn][kf + c0 + 8]);
                unsigned bl0 = *reinterpret_cast<const unsigned*>(&Bl[bn][kf + c0]);
                unsigned bl1 = *reinterpret_cast<const unsigned*>(&Bl[bn][kf + c0 + 8]);
#pragma unroll
                for (int im = 0; im < 2; im++) {
                    mma_bf16(d[im][jn][0], d[im][jn][1], d[im][jn][2], d[im][jn][3],
                             ah[im][0], ah[im][1], ah[im][2], ah[im][3], bh0, bh1);
                    mma_bf16(d[im][jn][0], d[im][jn][1], d[im][jn][2], d[im][jn][3],
                             ah[im][0], ah[im][1], ah[im][2], ah[im][3], bl0, bl1);
                    mma_bf16(d[im][jn][0], d[im][jn][1], d[im][jn][2], d[im][jn][3],
                             al[im][0], al[im][1], al[im][2], al[im][3], bh0, bh1);
                }
            }
        }
        __syncthreads();
    }

    // ---- epilogue: c0,c1 -> row g; c2,c3 -> row g+8; cols c0,c0+1
#pragma unroll
    for (int im = 0; im < 2; im++) {
        int r0 = rowBase + warp_m * 32 + im * 16 + g;
#pragma unroll
        for (int jn = 0; jn < 8; jn++) {
            int col = colBase + warp_n * 64 + jn * 8 + c0;
            if (r0 < M) {
                float2 v = make_float2(d[im][jn][0], d[im][jn][1]);
                *reinterpret_cast<float2*>(&C[(size_t)r0 * Hh + col]) = v;
            }
            if (r0 + 8 < M) {
                float2 v = make_float2(d[im][jn][2], d[im][jn][3]);
                *reinterpret_cast<float2*>(&C[(size_t)(r0 + 8) * Hh + col]) = v;
            }
        }
    }
}

// ---------------- CSR build (buffered) ----------------
__global__ void zero_cnt_kernel(int buf) {
    int i = blockIdx.x * blockDim.x + threadIdx.x;
    if (i < Nn) g_CNT[buf][i] = 0;
}

__global__ void count_kernel(const int* __restrict__ dst, int buf) {
    int e = blockIdx.x * blockDim.x + threadIdx.x;
    if (e < Ee) atomicAdd(&g_CNT[buf][dst[e]], 1);
}

__global__ __launch_bounds__(1024) void scan1_kernel(int buf) {
    __shared__ int sh[1024];
    int i = blockIdx.x * 1024 + threadIdx.x;
    int v = (i < Nn) ? g_CNT[buf][i] : 0;
    sh[threadIdx.x] = v;
    __syncthreads();
    for (int off = 1; off < 1024; off <<= 1) {
        int t = 0;
        if (threadIdx.x >= off) t = sh[threadIdx.x - off];
        __syncthreads();
        sh[threadIdx.x] += t;
        __syncthreads();
    }
    if (i < Nn) g_ROWPTR[buf][i] = sh[threadIdx.x] - v;
    if (threadIdx.x == 1023) g_BSUM[buf][blockIdx.x] = sh[1023];
}

__global__ void scan2_kernel(int buf) {
    if (threadIdx.x == 0 && blockIdx.x == 0) {
        int s = 0;
        for (int b = 0; b < SCAN_BLOCKS; b++) {
            int t = g_BSUM[buf][b]; g_BSUM[buf][b] = s; s += t;
        }
    }
}

__global__ void scan3_kernel(int buf) {
    int i = blockIdx.x * blockDim.x + threadIdx.x;
    if (i < Nn) {
        int r = g_ROWPTR[buf][i] + g_BSUM[buf][i >> 10];
        g_ROWPTR[buf][i] = r;
        g_CURS[buf][i]   = r;
        g_DINV[buf][i]   = rsqrtf((float)(g_CNT[buf][i] + 1));
    }
    if (i == 0) g_ROWPTR[buf][Nn] = Ee;
}

__global__ void fill_kernel(const int* __restrict__ src,
                            const int* __restrict__ dst, int buf) {
    int e = blockIdx.x * blockDim.x + threadIdx.x;
    if (e < Ee) {
        int d = dst[e], s = src[e];
        int slot = atomicAdd(&g_CURS[buf][d], 1);
        g_COL[buf][slot] = s;
        g_NRM[buf][slot] = g_DINV[buf][s] * g_DINV[buf][d];
    }
}

// ---------------- pull layer 1 (all nodes) ----------------
__global__ __launch_bounds__(256) void pull_l1_kernel(const float* __restrict__ b1,
                                                      int buf, int hbuf) {
    int warp = (blockIdx.x * blockDim.x + threadIdx.x) >> 5;
    int lane = threadIdx.x & 31;
    if (warp >= Nn) return;
    int i = warp;
    int beg = g_ROWPTR[buf][i], end = g_ROWPTR[buf][i + 1];
    const int*   COL = g_COL[buf];
    const float* NRM = g_NRM[buf];
    const float4* XW = reinterpret_cast<const float4*>(g_XW1);

    float4 a0 = make_float4(0.f, 0.f, 0.f, 0.f);
    float4 a1 = make_float4(0.f, 0.f, 0.f, 0.f);

    int e = beg;
    for (; e + 3 < end; e += 4) {
        int   s0 = COL[e],   s1 = COL[e + 1], s2 = COL[e + 2], s3 = COL[e + 3];
        float w0 = NRM[e],   w1 = NRM[e + 1], w2 = NRM[e + 2], w3 = NRM[e + 3];
        float4 v00 = XW[(size_t)s0 * 64 + lane];
        float4 v01 = XW[(size_t)s0 * 64 + 32 + lane];
        float4 v10 = XW[(size_t)s1 * 64 + lane];
        float4 v11 = XW[(size_t)s1 * 64 + 32 + lane];
        float4 v20 = XW[(size_t)s2 * 64 + lane];
        float4 v21 = XW[(size_t)s2 * 64 + 32 + lane];
        float4 v30 = XW[(size_t)s3 * 64 + lane];
        float4 v31 = XW[(size_t)s3 * 64 + 32 + lane];
        fma4v(a0, v00, w0); fma4v(a1, v01, w0);
        fma4v(a0, v10, w1); fma4v(a1, v11, w1);
        fma4v(a0, v20, w2); fma4v(a1, v21, w2);
        fma4v(a0, v30, w3); fma4v(a1, v31, w3);
    }
    for (; e < end; e++) {
        int s0 = COL[e]; float w0 = NRM[e];
        float4 v0 = XW[(size_t)s0 * 64 + lane];
        float4 v1 = XW[(size_t)s0 * 64 + 32 + lane];
        fma4v(a0, v0, w0); fma4v(a1, v1, w0);
    }

    float di = g_DINV[buf][i];
    float d2 = di * di;
    float4 s0 = XW[(size_t)i * 64 + lane];
    float4 s1 = XW[(size_t)i * 64 + 32 + lane];
    const float4* Bv = reinterpret_cast<const float4*>(b1);
    float4 bb0 = Bv[lane], bb1 = Bv[32 + lane];

    float4 o0, o1;
    o0.x = fmaxf(fmaf(s0.x, d2, a0.x) + bb0.x, 0.f);
    o0.y = fmaxf(fmaf(s0.y, d2, a0.y) + bb0.y, 0.f);
    o0.z = fmaxf(fmaf(s0.z, d2, a0.z) + bb0.z, 0.f);
    o0.w = fmaxf(fmaf(s0.w, d2, a0.w) + bb0.w, 0.f);
    o1.x = fmaxf(fmaf(s1.x, d2, a1.x) + bb1.x, 0.f);
    o1.y = fmaxf(fmaf(s1.y, d2, a1.y) + bb1.y, 0.f);
    o1.z = fmaxf(fmaf(s1.z, d2, a1.z) + bb1.z, 0.f);
    o1.w = fmaxf(fmaf(s1.w, d2, a1.w) + bb1.w, 0.f);

    float4* H = reinterpret_cast<float4*>(g_H1[hbuf]);
    H[(size_t)i * 64 + lane]      = o0;
    H[(size_t)i * 64 + 32 + lane] = o1;
}

// ---------------- pull layer 2 (POST ROWS ONLY) ----------------
__global__ __launch_bounds__(256) void pull_l2_kernel(
    const float* __restrict__ b2, const int* __restrict__ post_idx,
    int buf, int hbuf, int sidx)
{
    int warp = (blockIdx.x * blockDim.x + threadIdx.x) >> 5;
    int lane = threadIdx.x & 31;
    if (warp >= Pp) return;
    int p = warp;
    int i = post_idx[p];
    int beg = g_ROWPTR[buf][i], end = g_ROWPTR[buf][i + 1];
    const int*   COL = g_COL[buf];
    const float* NRM = g_NRM[buf];
    const float4* HW = reinterpret_cast<const float4*>(g_HW2[hbuf]);

    float4 a0 = make_float4(0.f, 0.f, 0.f, 0.f);
    float4 a1 = make_float4(0.f, 0.f, 0.f, 0.f);

    int e = beg;
    for (; e + 3 < end; e += 4) {
        int   s0 = COL[e],   s1 = COL[e + 1], s2 = COL[e + 2], s3 = COL[e + 3];
        float w0 = NRM[e],   w1 = NRM[e + 1], w2 = NRM[e + 2], w3 = NRM[e + 3];
        float4 v00 = HW[(size_t)s0 * 64 + lane];
        float4 v01 = HW[(size_t)s0 * 64 + 32 + lane];
        float4 v10 = HW[(size_t)s1 * 64 + lane];
        float4 v11 = HW[(size_t)s1 * 64 + 32 + lane];
        float4 v20 = HW[(size_t)s2 * 64 + lane];
        float4 v21 = HW[(size_t)s2 * 64 + 32 + lane];
        float4 v30 = HW[(size_t)s3 * 64 + lane];
        float4 v31 = HW[(size_t)s3 * 64 + 32 + lane];
        fma4v(a0, v00, w0); fma4v(a1, v01, w0);
        fma4v(a0, v10, w1); fma4v(a1, v11, w1);
        fma4v(a0, v20, w2); fma4v(a1, v21, w2);
        fma4v(a0, v30, w3); fma4v(a1, v31, w3);
    }
    for (; e < end; e++) {
        int s0 = COL[e]; float w0 = NRM[e];
        float4 v0 = HW[(size_t)s0 * 64 + lane];
        float4 v1 = HW[(size_t)s0 * 64 + 32 + lane];
        fma4v(a0, v0, w0); fma4v(a1, v1, w0);
    }

    float di = g_DINV[buf][i];
    float d2 = di * di;
    float4 s0 = HW[(size_t)i * 64 + lane];
    float4 s1 = HW[(size_t)i * 64 + 32 + lane];
    const float4* Bv = reinterpret_cast<const float4*>(b2);
    float4 bb0 = Bv[lane], bb1 = Bv[32 + lane];
    const float4* H = reinterpret_cast<const float4*>(g_H1[hbuf]);
    float4 h0 = H[(size_t)i * 64 + lane];
    float4 h1 = H[(size_t)i * 64 + 32 + lane];

    float4 r0, r1;
    r0.x = fmaf(s0.x, d2, a0.x) + bb0.x + h0.x;
    r0.y = fmaf(s0.y, d2, a0.y) + bb0.y + h0.y;
    r0.z = fmaf(s0.z, d2, a0.z) + bb0.z + h0.z;
    r0.w = fmaf(s0.w, d2, a0.w) + bb0.w + h0.w;
    r1.x = fmaf(s1.x, d2, a1.x) + bb1.x + h1.x;
    r1.y = fmaf(s1.y, d2, a1.y) + bb1.y + h1.y;
    r1.z = fmaf(s1.z, d2, a1.z) + bb1.z + h1.z;
    r1.w = fmaf(s1.w, d2, a1.w) + bb1.w + h1.w;

    float4* ACC = reinterpret_cast<float4*>(g_ACCS[sidx]);
    ACC[(size_t)p * 64 + lane]      = r0;
    ACC[(size_t)p * 64 + 32 + lane] = r1;
}

// ---------------- classifier ----------------
__global__ __launch_bounds__(128) void classifier_kernel(
    const float* __restrict__ Wc1, const float* __restrict__ bc1,
    const float* __restrict__ Wc2, const float* __restrict__ bc2,
    float* __restrict__ out)
{
    __shared__ float post[Hh];
    __shared__ float red[128];
    int p = blockIdx.x;
    int t = threadIdx.x;
    const float* r0 = &g_ACCS[0][(size_t)p * Hh];
    const float* r1 = &g_ACCS[1][(size_t)p * Hh];
    const float* r2 = &g_ACCS[2][(size_t)p * Hh];
    const float* r3 = &g_ACCS[3][(size_t)p * Hh];
    post[t]       = (r0[t]       + r1[t]       + r2[t]       + r3[t])       * 0.25f;
    post[t + 128] = (r0[t + 128] + r1[t + 128] + r2[t + 128] + r3[t + 128]) * 0.25f;
    __syncthreads();

    float acc = bc1[t];
#pragma unroll 8
    for (int j = 0; j < Hh; j++)
        acc = fmaf(post[j], Wc1[(size_t)j * 128 + t], acc);
    acc = fmaxf(acc, 0.f);
    float v = acc * Wc2[t];

    red[t] = v;
    __syncthreads();
    for (int off = 64; off > 0; off >>= 1) {
        if (t < off) red[t] += red[t + off];
        __syncthreads();
    }
    if (t == 0) {
        float lg = red[0] + bc2[0];
        out[p] = 1.f / (1.f + expf(-lg));
    }
}

// ---------------- launch: 3-stream pipelined schedule ----------------
static cudaStream_t s_csr = nullptr;   // CSR builds + pull_l2
static cudaStream_t s_pull = nullptr;  // pull_l1
static cudaEvent_t  s_evRoot, s_evXW1;
static cudaEvent_t  s_evCsr[Ss], s_evPl1[Ss], s_evG[Ss], s_evPl2[Ss];

static void build_csr(const int* EI, int s, cudaStream_t st) {
    const int nblk_node = (Nn + 255) / 256;
    const int nblk_edge = Ee / 256;
    int buf = s & 1;
    const int* src = EI + (size_t)s * 2 * Ee;
    const int* dst = src + Ee;
    zero_cnt_kernel<<<nblk_node, 256, 0, st>>>(buf);
    count_kernel<<<nblk_edge, 256, 0, st>>>(dst, buf);
    scan1_kernel<<<SCAN_BLOCKS, 1024, 0, st>>>(buf);
    scan2_kernel<<<1, 32, 0, st>>>(buf);
    scan3_kernel<<<nblk_node, 256, 0, st>>>(buf);
    fill_kernel<<<nblk_edge, 256, 0, st>>>(src, dst, buf);
}

extern "C" void kernel_launch(void* const* d_in, const int* in_sizes, int n_in,
                              void* d_out, int out_size)
{
    const float* X        = (const float*)d_in[0];
    const int*   EI       = (const int*)  d_in[1];
    const int*   post_idx = (const int*)  d_in[2];
    const float* W1       = (const float*)d_in[3];
    const float* b1       = (const float*)d_in[4];
    const float* W2       = (const float*)d_in[5];
    const float* b2       = (const float*)d_in[6];
    const float* Wc1      = (const float*)d_in[7];
    const float* bc1      = (const float*)d_in[8];
    const float* Wc2      = (const float*)d_in[9];
    const float* bc2      = (const float*)d_in[10];
    float* out = (float*)d_out;

    if (!s_csr) {
        cudaStreamCreateWithFlags(&s_csr, cudaStreamNonBlocking);
        cudaStreamCreateWithFlags(&s_pull, cudaStreamNonBlocking);
        cudaEventCreateWithFlags(&s_evRoot, cudaEventDisableTiming);
        cudaEventCreateWithFlags(&s_evXW1, cudaEventDisableTiming);
        for (int s = 0; s < Ss; s++) {
            cudaEventCreateWithFlags(&s_evCsr[s], cudaEventDisableTiming);
            cudaEventCreateWithFlags(&s_evPl1[s], cudaEventDisableTiming);
            cudaEventCreateWithFlags(&s_evG[s], cudaEventDisableTiming);
            cudaEventCreateWithFlags(&s_evPl2[s], cudaEventDisableTiming);
        }
    }

    dim3 gemm_grid((Nn + BMg - 1) / BMg, Hh / BNg);   // (782, 2)
    const int nblk_pl1 = (Nn + 7) / 8;
    const int nblk_pl2 = (Pp + 7) / 8;

    // fork
    cudaEventRecord(s_evRoot, 0);
    cudaStreamWaitEvent(s_csr, s_evRoot, 0);
    cudaStreamWaitEvent(s_pull, s_evRoot, 0);

    // csr stream: CSR(0), CSR(1)
    build_csr(EI, 0, s_csr);
    cudaEventRecord(s_evCsr[0], s_csr);
    build_csr(EI, 1, s_csr);
    cudaEventRecord(s_evCsr[1], s_csr);

    // main: XW1 = X @ W1
    tc_gemm_kernel<<<gemm_grid, 256>>>(X, W1, 0, 0, Nn, Dd);
    cudaEventRecord(s_evXW1, 0);

    // pull stream: pl1(0), pl1(1)
    cudaStreamWaitEvent(s_pull, s_evXW1, 0);
    cudaStreamWaitEvent(s_pull, s_evCsr[0], 0);
    pull_l1_kernel<<<nblk_pl1, 256, 0, s_pull>>>(b1, 0, 0);
    cudaEventRecord(s_evPl1[0], s_pull);
    cudaStreamWaitEvent(s_pull, s_evCsr[1], 0);
    pull_l1_kernel<<<nblk_pl1, 256, 0, s_pull>>>(b1, 1, 1);
    cudaEventRecord(s_evPl1[1], s_pull);

    for (int s = 0; s < Ss; s++) {
        int buf = s & 1;
        cudaStreamWaitEvent(0, s_evPl1[s], 0);
        if (s >= 2) cudaStreamWaitEvent(0, s_evPl2[s - 2], 0);
        tc_gemm_kernel<<<gemm_grid, 256>>>(nullptr, W2, 1, buf, Nn, Hh);
        cudaEventRecord(s_evG[s], 0);

        cudaStreamWaitEvent(s_csr, s_evG[s], 0);
        pull_l2_kernel<<<nblk_pl2, 256, 0, s_csr>>>(b2, post_idx, buf, buf, s);
        cudaEventRecord(s_evPl2[s], s_csr);

        if (s + 2 < Ss) {
            cudaStreamWaitEvent(s_csr, s_evPl1[s], 0);
            build_csr(EI, s + 2, s_csr);
            cudaEventRecord(s_evCsr[s + 2], s_csr);

            cudaStreamWaitEvent(s_pull, s_evCsr[s + 2], 0);
            cudaStreamWaitEvent(s_pull, s_evG[s], 0);
            cudaStreamWaitEvent(s_pull, s_evPl2[s], 0);
            pull_l1_kernel<<<nblk_pl1, 256, 0, s_pull>>>(b1, buf, buf);
            cudaEventRecord(s_evPl1[s + 2], s_pull);
        }
    }

    for (int s = 0; s < Ss; s++)
        cudaStreamWaitEvent(0, s_evPl2[s], 0);
    classifier_kernel<<<Pp, 128>>>(Wc1, bc1, Wc2, bc2, out);
}